// round 2
// baseline (speedup 1.0000x reference)
#include <cuda_runtime.h>

// Problem constants (match reference setup_inputs)
#define B_ 8
#define H_ 512
#define W_ 512
#define N_ 128
#define HW_ (H_ * W_)
#define PR_MIN_ 0.2f
#define REF_RES_ 0.2f

// Scratch (no allocations allowed in kernel_launch)
__device__ float4 g_ctr[B_ * N_];          // {cy_f, cx_f, inv2s2, 0}
__device__ float  g_part_sm[B_ * H_];      // per-row-block partial sum of sm^2
__device__ float  g_part_hm[B_ * H_];      // per-row-block partial sum of (hm-gt)^2*mask

// ---------------------------------------------------------------------------
// Kernel 1: per-center prep. 8 blocks x 128 threads = one thread per (b, n).
// ---------------------------------------------------------------------------
__global__ void prep_kernel(const float* __restrict__ sm,
                            const float* __restrict__ gr,
                            const int*   __restrict__ centers)
{
    int i = blockIdx.x * blockDim.x + threadIdx.x;   // 0 .. B*N-1
    int b = i / N_;
    int cy = centers[i * 2 + 0];
    int cx = centers[i * 2 + 1];
    cy = min(max(cy, 0), H_ - 1);
    cx = min(max(cx, 0), W_ - 1);
    float s = sm[(size_t)b * HW_ + cy * W_ + cx];
    s = fmaxf(s, 0.0f);                               // relu
    float g = gr[b];
    float sigma = PR_MIN_ / g + s * REF_RES_ / g;     // same op order as reference
    float inv   = 1.0f / (2.0f * sigma * sigma);
    g_ctr[i] = make_float4((float)cy, (float)cx, inv, 0.0f);
}

// ---------------------------------------------------------------------------
// Kernel 2: main pass. One block per (b, y) row: 4096 blocks x 128 threads.
// Each thread computes 4 consecutive pixels:
//   q = min_n ((y-cy)^2 + (x-cx)^2) * inv2s2_n ;  gt = exp(-q)
// plus fused loss partial sums (deterministic block reduction).
// ---------------------------------------------------------------------------
__global__ void __launch_bounds__(128)
main_kernel(const float* __restrict__ hm,
            const float* __restrict__ smap,
            const float* __restrict__ mask,
            float* __restrict__ out)
{
    __shared__ float4 sp[N_];     // {cx, a_row, inv, 0}
    __shared__ float  r1[128];
    __shared__ float  r2[128];

    const int blk = blockIdx.x;
    const int b   = blk >> 9;       // / 512
    const int y   = blk & (H_ - 1);
    const int tid = threadIdx.x;

    // Precompute per-center row term a_n = (y - cy)^2 * inv
    {
        float4 c = g_ctr[b * N_ + tid];
        float dy = (float)y - c.x;
        sp[tid] = make_float4(c.y, dy * dy * c.z, c.z, 0.0f);
    }
    __syncthreads();

    const int   x0  = tid * 4;
    const float xf0 = (float)x0;

    float m0 = 3.0e38f, m1 = 3.0e38f, m2 = 3.0e38f, m3 = 3.0e38f;

    #pragma unroll 8
    for (int n = 0; n < N_; n++) {
        float4 c = sp[n];
        float d0 = xf0 - c.x;
        float d1 = d0 + 1.0f;
        float d2 = d0 + 2.0f;
        float d3 = d0 + 3.0f;
        float q0 = fmaf(d0, d0 * c.z, c.y);
        float q1 = fmaf(d1, d1 * c.z, c.y);
        float q2 = fmaf(d2, d2 * c.z, c.y);
        float q3 = fmaf(d3, d3 * c.z, c.y);
        m0 = fminf(m0, q0);
        m1 = fminf(m1, q1);
        m2 = fminf(m2, q2);
        m3 = fminf(m3, q3);
    }

    float g0 = __expf(-m0);
    float g1 = __expf(-m1);
    float g2 = __expf(-m2);
    float g3 = __expf(-m3);

    const size_t base = (size_t)b * HW_ + (size_t)y * W_ + x0;

    float4 h  = *reinterpret_cast<const float4*>(hm   + base);
    float4 mk = *reinterpret_cast<const float4*>(mask + base);
    float4 sv = *reinterpret_cast<const float4*>(smap + base);

    float ssum = sv.x * sv.x + sv.y * sv.y + sv.z * sv.z + sv.w * sv.w;

    float e0 = h.x - g0;
    float e1 = h.y - g1;
    float e2 = h.z - g2;
    float e3 = h.w - g3;
    float hsum = e0 * e0 * mk.x + e1 * e1 * mk.y + e2 * e2 * mk.z + e3 * e3 * mk.w;

    // gts output lives at out + 2 (only 8-byte aligned) -> float2 stores
    float* og = out + 2 + base;
    reinterpret_cast<float2*>(og)[0] = make_float2(g0, g1);
    reinterpret_cast<float2*>(og)[1] = make_float2(g2, g3);

    // Deterministic block reduction
    r1[tid] = ssum;
    r2[tid] = hsum;
    __syncthreads();
    #pragma unroll
    for (int s = 64; s > 0; s >>= 1) {
        if (tid < s) {
            r1[tid] += r1[tid + s];
            r2[tid] += r2[tid + s];
        }
        __syncthreads();
    }
    if (tid == 0) {
        g_part_sm[blk] = r1[0];
        g_part_hm[blk] = r2[0];
    }
}

// ---------------------------------------------------------------------------
// Kernel 3: final deterministic reduction of 4096 row partials -> scalars.
// ---------------------------------------------------------------------------
__global__ void finish_kernel(float* __restrict__ out)
{
    __shared__ float r1[1024];
    __shared__ float r2[1024];
    int tid = threadIdx.x;
    float a = 0.0f, c = 0.0f;
    #pragma unroll
    for (int i = tid; i < B_ * H_; i += 1024) {
        a += g_part_sm[i];
        c += g_part_hm[i];
    }
    r1[tid] = a;
    r2[tid] = c;
    __syncthreads();
    #pragma unroll
    for (int s = 512; s > 0; s >>= 1) {
        if (tid < s) {
            r1[tid] += r1[tid + s];
            r2[tid] += r2[tid + s];
        }
        __syncthreads();
    }
    if (tid == 0) {
        const float inv_total = 1.0f / (float)((size_t)B_ * HW_);
        out[0] = r1[0] * inv_total;   // mean scale loss
        out[1] = r2[0] * inv_total;   // mean heatmap loss
    }
}

// ---------------------------------------------------------------------------
extern "C" void kernel_launch(void* const* d_in, const int* in_sizes, int n_in,
                              void* d_out, int out_size)
{
    const float* pred_hm = (const float*)d_in[0];
    const float* pred_sm = (const float*)d_in[1];
    const float* gres    = (const float*)d_in[2];
    const float* mask    = (const float*)d_in[3];
    const int*   centers = (const int*)d_in[4];
    float* out = (float*)d_out;

    prep_kernel<<<B_, N_>>>(pred_sm, gres, centers);
    main_kernel<<<B_ * H_, 128>>>(pred_hm, pred_sm, mask, out);
    finish_kernel<<<1, 1024>>>(out);
}

// round 4
// speedup vs baseline: 2.8216x; 2.8216x over previous
#include <cuda_runtime.h>

// Problem constants (match reference setup_inputs)
#define B_ 8
#define H_ 512
#define W_ 512
#define N_ 128
#define HW_ (H_ * W_)
#define GRID_ (B_ * H_)
#define QCUT 50.0f   // exp(-50) ~ 2e-22: dropping such centers is invisible vs 1e-3 tol

// Scratch (no allocations allowed)
__device__ float g_part_sm[GRID_];
__device__ float g_part_hm[GRID_];
__device__ unsigned int g_count = 0;   // wraps via atomicInc -> auto-reset per replay

// ---------------------------------------------------------------------------
// Single fused kernel. One block per (b, y) row: 4096 blocks x 128 threads.
//  - inline per-center prep (sigma from gathered scale map)
//  - prune centers whose best-case row q = (y-cy)^2 * inv > QCUT, compact
//  - per-pixel EXACT form: d = x - cx; q = min_n fmaf(d, d*inv, a); gt = exp(-q)
//  - fused losses, deterministic reductions; last block finishes scalars
// ---------------------------------------------------------------------------
__global__ void __launch_bounds__(128)
fused_kernel(const float* __restrict__ hm,
             const float* __restrict__ smap,
             const float* __restrict__ gres,
             const float* __restrict__ mask,
             const int*   __restrict__ centers,
             float* __restrict__ out)
{
    __shared__ float4 sp[N_];          // compacted {cx, a_row, inv, 0}
    __shared__ int    warp_cnt[4];
    __shared__ int    warp_off[4];
    __shared__ int    s_cnt;
    __shared__ float  r1[128];
    __shared__ float  r2[128];

    const int blk = blockIdx.x;
    const int b   = blk >> 9;          // / 512
    const int y   = blk & (H_ - 1);
    const int tid = threadIdx.x;
    const int wid = tid >> 5;
    const int lane = tid & 31;

    const size_t base = (size_t)b * HW_ + (size_t)y * W_ + tid * 4;

    // Issue streaming loads early to overlap with center prep.
    const float4 h  = *reinterpret_cast<const float4*>(hm   + base);
    const float4 mk = *reinterpret_cast<const float4*>(mask + base);
    const float4 sv = *reinterpret_cast<const float4*>(smap + base);

    // ---- per-center prep + prune + compact (thread tid <-> center tid) ----
    {
        int2 c = reinterpret_cast<const int2*>(centers)[b * N_ + tid];
        int cy = min(max(c.x, 0), H_ - 1);
        int cx = min(max(c.y, 0), W_ - 1);
        float s = fmaxf(__ldg(smap + (size_t)b * HW_ + cy * W_ + cx), 0.0f);
        float g = gres[b];
        float sigma = 0.2f / g + s * 0.2f / g;        // same op order as reference
        float inv   = 1.0f / (2.0f * sigma * sigma);
        float dy = (float)(y - cy);
        float a  = dy * dy * inv;                      // best-case q in this row
        bool keep = (a <= QCUT);

        unsigned msk = __ballot_sync(0xffffffffu, keep);
        int pos = __popc(msk & ((1u << lane) - 1u));
        if (lane == 0) warp_cnt[wid] = __popc(msk);
        __syncthreads();
        if (tid == 0) {
            int o = 0;
            #pragma unroll
            for (int w = 0; w < 4; w++) { warp_off[w] = o; o += warp_cnt[w]; }
            s_cnt = o;
        }
        __syncthreads();
        if (keep)
            sp[warp_off[wid] + pos] = make_float4((float)cx, a, inv, 0.0f);
    }
    __syncthreads();
    const int cnt = s_cnt;

    // ---- min over surviving centers (exact differenced form) ----
    const float x0 = (float)(tid * 4);
    float m0 = 3.0e38f, m1 = 3.0e38f, m2 = 3.0e38f, m3 = 3.0e38f;

    #pragma unroll 4
    for (int n = 0; n < cnt; n++) {
        float4 c = sp[n];
        float d0 = x0 - c.x;           // exact: both are small integers in fp32
        float d1 = d0 + 1.0f;
        float d2 = d0 + 2.0f;
        float d3 = d0 + 3.0f;
        m0 = fminf(m0, fmaf(d0, d0 * c.z, c.y));
        m1 = fminf(m1, fmaf(d1, d1 * c.z, c.y));
        m2 = fminf(m2, fmaf(d2, d2 * c.z, c.y));
        m3 = fminf(m3, fmaf(d3, d3 * c.z, c.y));
    }

    const float g0 = __expf(-m0);
    const float g1 = __expf(-m1);
    const float g2 = __expf(-m2);
    const float g3 = __expf(-m3);

    // ---- fused losses ----
    float ssum = sv.x * sv.x + sv.y * sv.y + sv.z * sv.z + sv.w * sv.w;
    float e0 = h.x - g0, e1 = h.y - g1, e2 = h.z - g2, e3 = h.w - g3;
    float hsum = e0 * e0 * mk.x + e1 * e1 * mk.y + e2 * e2 * mk.z + e3 * e3 * mk.w;

    // gts output at out + 2 (8-byte aligned) -> float2 stores
    float* og = out + 2 + base;
    reinterpret_cast<float2*>(og)[0] = make_float2(g0, g1);
    reinterpret_cast<float2*>(og)[1] = make_float2(g2, g3);

    // ---- deterministic block reduction ----
    r1[tid] = ssum;
    r2[tid] = hsum;
    __syncthreads();
    #pragma unroll
    for (int s = 64; s > 0; s >>= 1) {
        if (tid < s) { r1[tid] += r1[tid + s]; r2[tid] += r2[tid + s]; }
        __syncthreads();
    }
    __shared__ bool amLast;
    if (tid == 0) {
        g_part_sm[blk] = r1[0];
        g_part_hm[blk] = r2[0];
        __threadfence();
        unsigned v = atomicInc(&g_count, GRID_ - 1);   // wraps to 0 -> replay-safe
        amLast = (v == GRID_ - 1);
    }
    __syncthreads();

    // ---- last-finishing block: deterministic final reduction ----
    if (amLast) {
        float a = 0.0f, c = 0.0f;
        #pragma unroll
        for (int i = tid; i < GRID_; i += 128) {
            a += __ldcg(&g_part_sm[i]);   // bypass L1: see all blocks' stores
            c += __ldcg(&g_part_hm[i]);
        }
        r1[tid] = a;
        r2[tid] = c;
        __syncthreads();
        #pragma unroll
        for (int s = 64; s > 0; s >>= 1) {
            if (tid < s) { r1[tid] += r1[tid + s]; r2[tid] += r2[tid + s]; }
            __syncthreads();
        }
        if (tid == 0) {
            const float inv_total = 1.0f / (float)((size_t)B_ * HW_);
            out[0] = r1[0] * inv_total;
            out[1] = r2[0] * inv_total;
        }
    }
}

// ---------------------------------------------------------------------------
extern "C" void kernel_launch(void* const* d_in, const int* in_sizes, int n_in,
                              void* d_out, int out_size)
{
    const float* pred_hm = (const float*)d_in[0];
    const float* pred_sm = (const float*)d_in[1];
    const float* gres    = (const float*)d_in[2];
    const float* mask    = (const float*)d_in[3];
    const int*   centers = (const int*)d_in[4];
    float* out = (float*)d_out;

    fused_kernel<<<GRID_, 128>>>(pred_hm, pred_sm, gres, mask, centers, out);
}